// round 11
// baseline (speedup 1.0000x reference)
#include <cuda_runtime.h>
#include <cstdint>
#include <cstddef>

#define BB   128
#define SS   50
#define DIMN 128
#define N0   50
#define N1   600
#define N2   1200

// ---------------- scratch (static device globals; no allocation) ----------------
__device__ float g_sess[BB * DIMN];
__device__ float g_ev0[BB * N0 * DIMN];
__device__ float g_ev1[BB * N1 * DIMN];
__device__ float g_ev2[(size_t)BB * N2 * DIMN];
__device__ float g_agg[BB * N1 * DIMN];
__device__ float g_o0a[BB * N0 * DIMN];
__device__ float g_o0b[BB * N1 * DIMN];
__device__ float g_score[BB * N1 * 2];     // max 153600 scores

__device__ __forceinline__ float leaky(float x) { return x >= 0.f ? x : 0.2f * x; }

__device__ __forceinline__ uint32_t f2tf(float x) {
    uint32_t o;
    asm("cvt.rna.tf32.f32 %0, %1;" : "=r"(o) : "f"(x));
    return o;
}

__device__ __forceinline__ void mma_tf32(float c[4], uint32_t a0, uint32_t a1, uint32_t a2,
                                         uint32_t a3, uint32_t b0, uint32_t b1) {
    asm volatile(
        "mma.sync.aligned.m16n8k8.row.col.f32.tf32.tf32.f32 "
        "{%0,%1,%2,%3}, {%4,%5,%6,%7}, {%8,%9}, {%0,%1,%2,%3};\n"
        : "+f"(c[0]), "+f"(c[1]), "+f"(c[2]), "+f"(c[3])
        : "r"(a0), "r"(a1), "r"(a2), "r"(a3), "r"(b0), "r"(b1));
}

#define AST 36    // A smem stride (floats), 4 mod 32 -> conflict-free frag loads
#define BST 136   // B smem stride (floats), 8 mod 32 -> conflict-free frag loads

// ---------------- session mean embedding ----------------
__global__ void sess_kernel(const int* __restrict__ item, const int* __restrict__ mask,
                            const float* __restrict__ emb) {
    int b = blockIdx.x, d = threadIdx.x;
    float acc = 0.f, ms = 0.f;
    for (int s = 0; s < SS; s++) {
        float m = (float)mask[b * SS + s];
        ms += m;
        int node = item[b * SS + s];
        acc += m * emb[(size_t)node * DIMN + d];
    }
    g_sess[b * DIMN + d] = acc / ms;
}

// ---------------- gather ev0/ev1/ev2 (warp per row, float4) ----------------
__global__ void gather_kernel(const int* __restrict__ inputs, const int* __restrict__ first_adj,
                              const int* __restrict__ adj_all, const float* __restrict__ emb) {
    int warp = (blockIdx.x * blockDim.x + threadIdx.x) >> 5;
    int lane = threadIdx.x & 31;
    const int R0 = BB * N0, R1 = BB * N1, R2 = BB * N2;
    if (warp >= R0 + R1 + R2) return;
    int node;
    float* dst;
    if (warp < R0) {
        node = inputs[warp];
        dst = g_ev0 + (size_t)warp * DIMN;
    } else if (warp < R0 + R1) {
        int r1 = warp - R0;
        node = first_adj[r1];
        dst = g_ev1 + (size_t)r1 * DIMN;
    } else {
        int r2 = warp - R0 - R1;
        int b = r2 / N2, j = r2 % N2;
        int n = j >> 1, jj = j & 1;
        int p = first_adj[b * N1 + n];
        node = adj_all[p * 2 + jj];
        dst = g_ev2 + (size_t)r2 * DIMN;
    }
    const float4* src = (const float4*)(emb + (size_t)node * DIMN);
    ((float4*)dst)[lane] = src[lane];
}

// ---------------- local GAT (one block per batch element) ----------------
__global__ __launch_bounds__(256) void local_kernel(const int* __restrict__ adj,
                                                    const float* __restrict__ a_local,
                                                    float* __restrict__ out) {
    __shared__ __align__(16) float hs[SS * DIMN];
    __shared__ __align__(16) float als[4 * DIMN];
    __shared__ float att[SS][SS];
    int b = blockIdx.x, t = threadIdx.x;
    for (int i = t; i < SS * DIMN; i += 256) hs[i] = g_ev0[(size_t)b * SS * DIMN + i];
    for (int i = t; i < 4 * DIMN; i += 256) als[i] = a_local[i];
    __syncthreads();
    for (int p = t; p < SS * SS; p += 256) {
        int i = p / SS, j = p % SS;
        int a = adj[(size_t)b * SS * SS + p];
        float v;
        if (a == 0) {
            v = -9e15f;
        } else {
            int k = a - 1;
            const float4* hi = (const float4*)(hs + i * DIMN);
            const float4* hj = (const float4*)(hs + j * DIMN);
            const float4* ak = (const float4*)(als + k * DIMN);
            float acc = 0.f;
#pragma unroll
            for (int q = 0; q < 32; q++) {
                float4 x = hi[q], y = hj[q], z = ak[q];
                acc += x.x * y.x * z.x + x.y * y.y * z.y + x.z * y.z * z.z + x.w * y.w * z.w;
            }
            v = leaky(acc);
        }
        att[i][j] = v;
    }
    __syncthreads();
    int w = t >> 5, lane = t & 31;
    for (int i = w; i < SS; i += 8) {
        float v0 = att[i][lane];
        float v1 = (lane + 32 < SS) ? att[i][lane + 32] : -3.4e38f;
        float m = fmaxf(v0, v1);
        for (int off = 16; off; off >>= 1) m = fmaxf(m, __shfl_xor_sync(0xffffffffu, m, off));
        float e0 = expf(v0 - m);
        float e1 = (lane + 32 < SS) ? expf(v1 - m) : 0.f;
        float s = e0 + e1;
        for (int off = 16; off; off >>= 1) s += __shfl_xor_sync(0xffffffffu, s, off);
        att[i][lane] = e0 / s;
        if (lane + 32 < SS) att[i][lane + 32] = e1 / s;
    }
    __syncthreads();
    for (int idx = t; idx < SS * DIMN; idx += 256) {
        int i = idx >> 7, d = idx & 127;
        float acc = 0.f;
        for (int j = 0; j < SS; j++) acc += att[i][j] * hs[j * DIMN + d];
        out[(size_t)b * SS * DIMN + idx] = acc;
    }
}

// ---------------- attention-score GEMM (tf32 tensor cores) ----------------
// S[row] = sum_e leaky( sum_d (sess[b,d]*neigh[row,d]) * W1[d,e] ) * w2[e]
// Tile: 128 rows x N=128, K=128 in 4 chunks of 32. 8 warps, warp = 16 rows.
__global__ __launch_bounds__(256, 2) void score_gemm(const float* __restrict__ neigh,
                                                     const float* __restrict__ w1,
                                                     const float* __restrict__ w2,
                                                     int rowsPerB, int total) {
    __shared__ __align__(16) float As[128 * AST];
    __shared__ __align__(16) float Bs[32 * BST];
    __shared__ float w2s[DIMN];
    int t = threadIdx.x;
    int warp = t >> 5, lane = t & 31, gr = lane >> 2, ctg = lane & 3;
    if (t < DIMN) w2s[t] = w2[t];
    int rowBase0 = blockIdx.x * 128;

    float c[16][4];
#pragma unroll
    for (int nt = 0; nt < 16; nt++)
#pragma unroll
        for (int q = 0; q < 4; q++) c[nt][q] = 0.f;

    for (int kc = 0; kc < 4; kc++) {
        // load A chunk (128 x 32): X = sess (.) neigh, converted to tf32
#pragma unroll
        for (int i = 0; i < 4; i++) {
            int id = t + i * 256;
            int r = id >> 3, c4 = (id & 7) * 4;
            int rr = rowBase0 + r;
            float4 v = make_float4(0.f, 0.f, 0.f, 0.f);
            if (rr < total) {
                int b = rr / rowsPerB;
                float4 nv = *(const float4*)(neigh + (size_t)rr * DIMN + kc * 32 + c4);
                float4 sv = *(const float4*)(g_sess + b * DIMN + kc * 32 + c4);
                v.x = nv.x * sv.x; v.y = nv.y * sv.y; v.z = nv.z * sv.z; v.w = nv.w * sv.w;
            }
            uint4 o;
            o.x = f2tf(v.x); o.y = f2tf(v.y); o.z = f2tf(v.z); o.w = f2tf(v.w);
            *(uint4*)(&As[r * AST + c4]) = o;
        }
        // load B chunk (32 x 128) from W1
#pragma unroll
        for (int i = 0; i < 4; i++) {
            int id = t + i * 256;
            int k = id >> 5, c4 = (id & 31) * 4;
            float4 wv = *(const float4*)(w1 + (size_t)(kc * 32 + k) * DIMN + c4);
            uint4 o;
            o.x = f2tf(wv.x); o.y = f2tf(wv.y); o.z = f2tf(wv.z); o.w = f2tf(wv.w);
            *(uint4*)(&Bs[k * BST + c4]) = o;
        }
        __syncthreads();
        int rb = warp * 16;
#pragma unroll
        for (int ks = 0; ks < 4; ks++) {
            int k0 = ks * 8;
            uint32_t a0 = __float_as_uint(As[(rb + gr) * AST + k0 + ctg]);
            uint32_t a1 = __float_as_uint(As[(rb + gr + 8) * AST + k0 + ctg]);
            uint32_t a2 = __float_as_uint(As[(rb + gr) * AST + k0 + ctg + 4]);
            uint32_t a3 = __float_as_uint(As[(rb + gr + 8) * AST + k0 + ctg + 4]);
#pragma unroll
            for (int nt = 0; nt < 16; nt++) {
                int n0 = nt * 8;
                uint32_t b0 = __float_as_uint(Bs[(k0 + ctg) * BST + n0 + gr]);
                uint32_t b1 = __float_as_uint(Bs[(k0 + ctg + 4) * BST + n0 + gr]);
                mma_tf32(c[nt], a0, a1, a2, a3, b0, b1);
            }
        }
        __syncthreads();
    }
    // epilogue: leaky, *w2, row-reduce
    float p0 = 0.f, p1 = 0.f;
#pragma unroll
    for (int nt = 0; nt < 16; nt++) {
        int col0 = nt * 8 + 2 * ctg;
        float w20 = w2s[col0], w21 = w2s[col0 + 1];
        p0 += leaky(c[nt][0]) * w20 + leaky(c[nt][1]) * w21;
        p1 += leaky(c[nt][2]) * w20 + leaky(c[nt][3]) * w21;
    }
    p0 += __shfl_xor_sync(0xffffffffu, p0, 1);
    p0 += __shfl_xor_sync(0xffffffffu, p0, 2);
    p1 += __shfl_xor_sync(0xffffffffu, p1, 1);
    p1 += __shfl_xor_sync(0xffffffffu, p1, 2);
    if (ctg == 0) {
        int r0 = rowBase0 + warp * 16 + gr;
        if (r0 < total) g_score[r0] = p0;
        if (r0 + 8 < total) g_score[r0 + 8] = p1;
    }
}

// ---------------- softmax over K + weighted aggregation (warp per node) ----------------
template <int K>
__global__ void softagg_kernel(const float* __restrict__ neigh, int nodes) {
    int warp = (blockIdx.x * blockDim.x + threadIdx.x) >> 5;
    int lane = threadIdx.x & 31;
    if (warp >= nodes) return;
    float s = (lane < K) ? g_score[warp * K + lane] : -3.4e38f;
    float m = s;
    for (int off = 16; off; off >>= 1) m = fmaxf(m, __shfl_xor_sync(0xffffffffu, m, off));
    float e = (lane < K) ? expf(s - m) : 0.f;
    float sum = e;
    for (int off = 16; off; off >>= 1) sum += __shfl_xor_sync(0xffffffffu, sum, off);
    float a = e / sum;
    float4 acc = make_float4(0.f, 0.f, 0.f, 0.f);
#pragma unroll
    for (int k = 0; k < K; k++) {
        float ak = __shfl_sync(0xffffffffu, a, k);
        float4 v = *(const float4*)(neigh + ((size_t)warp * K + k) * DIMN + lane * 4);
        acc.x += ak * v.x; acc.y += ak * v.y; acc.z += ak * v.z; acc.w += ak * v.w;
    }
    *(float4*)(g_agg + (size_t)warp * DIMN + lane * 4) = acc;
}

// ---------------- output transform GEMM: relu(concat(self,agg) @ W3 + bias) ----------------
// Tile: 128 rows x N=128, K=256 in 8 chunks of 32. ACC: 0 write, 1 accumulate into out.
template <int ACC>
__global__ __launch_bounds__(256, 2) void out_gemm(const float* __restrict__ self_,
                                                   const float* __restrict__ w3,
                                                   const float* __restrict__ bias,
                                                   float* __restrict__ out, int rows) {
    __shared__ __align__(16) float As[128 * AST];
    __shared__ __align__(16) float Bs[32 * BST];
    __shared__ float bs[DIMN];
    int t = threadIdx.x;
    int warp = t >> 5, lane = t & 31, gr = lane >> 2, ctg = lane & 3;
    if (t < DIMN) bs[t] = bias[t];
    int rowBase0 = blockIdx.x * 128;

    float c[16][4];
#pragma unroll
    for (int nt = 0; nt < 16; nt++)
#pragma unroll
        for (int q = 0; q < 4; q++) c[nt][q] = 0.f;

    for (int kc = 0; kc < 8; kc++) {
        const float* src = (kc < 4) ? self_ : g_agg;
        int dbase = (kc < 4) ? kc * 32 : (kc - 4) * 32;
#pragma unroll
        for (int i = 0; i < 4; i++) {
            int id = t + i * 256;
            int r = id >> 3, c4 = (id & 7) * 4;
            int rr = rowBase0 + r;
            float4 v = make_float4(0.f, 0.f, 0.f, 0.f);
            if (rr < rows) v = *(const float4*)(src + (size_t)rr * DIMN + dbase + c4);
            uint4 o;
            o.x = f2tf(v.x); o.y = f2tf(v.y); o.z = f2tf(v.z); o.w = f2tf(v.w);
            *(uint4*)(&As[r * AST + c4]) = o;
        }
#pragma unroll
        for (int i = 0; i < 4; i++) {
            int id = t + i * 256;
            int k = id >> 5, c4 = (id & 31) * 4;
            float4 wv = *(const float4*)(w3 + (size_t)(kc * 32 + k) * DIMN + c4);
            uint4 o;
            o.x = f2tf(wv.x); o.y = f2tf(wv.y); o.z = f2tf(wv.z); o.w = f2tf(wv.w);
            *(uint4*)(&Bs[k * BST + c4]) = o;
        }
        __syncthreads();
        int rb = warp * 16;
#pragma unroll
        for (int ks = 0; ks < 4; ks++) {
            int k0 = ks * 8;
            uint32_t a0 = __float_as_uint(As[(rb + gr) * AST + k0 + ctg]);
            uint32_t a1 = __float_as_uint(As[(rb + gr + 8) * AST + k0 + ctg]);
            uint32_t a2 = __float_as_uint(As[(rb + gr) * AST + k0 + ctg + 4]);
            uint32_t a3 = __float_as_uint(As[(rb + gr + 8) * AST + k0 + ctg + 4]);
#pragma unroll
            for (int nt = 0; nt < 16; nt++) {
                int n0 = nt * 8;
                uint32_t b0 = __float_as_uint(Bs[(k0 + ctg) * BST + n0 + gr]);
                uint32_t b1 = __float_as_uint(Bs[(k0 + ctg + 4) * BST + n0 + gr]);
                mma_tf32(c[nt], a0, a1, a2, a3, b0, b1);
            }
        }
        __syncthreads();
    }
    // epilogue: + bias, relu, store / accumulate
    int r0 = rowBase0 + warp * 16 + gr;
    int r1 = r0 + 8;
#pragma unroll
    for (int nt = 0; nt < 16; nt++) {
        int col0 = nt * 8 + 2 * ctg;
        float z00 = fmaxf(c[nt][0] + bs[col0], 0.f);
        float z01 = fmaxf(c[nt][1] + bs[col0 + 1], 0.f);
        float z10 = fmaxf(c[nt][2] + bs[col0], 0.f);
        float z11 = fmaxf(c[nt][3] + bs[col0 + 1], 0.f);
        if (r0 < rows) {
            if (ACC) {
                out[(size_t)r0 * DIMN + col0] += z00;
                out[(size_t)r0 * DIMN + col0 + 1] += z01;
            } else {
                out[(size_t)r0 * DIMN + col0] = z00;
                out[(size_t)r0 * DIMN + col0 + 1] = z01;
            }
        }
        if (r1 < rows) {
            if (ACC) {
                out[(size_t)r1 * DIMN + col0] += z10;
                out[(size_t)r1 * DIMN + col0 + 1] += z11;
            } else {
                out[(size_t)r1 * DIMN + col0] = z10;
                out[(size_t)r1 * DIMN + col0 + 1] = z11;
            }
        }
    }
}

// ---------------- launch ----------------
extern "C" void kernel_launch(void* const* d_in, const int* in_sizes, int n_in,
                              void* d_out, int out_size) {
    const int*   inputs    = (const int*)d_in[0];
    const int*   adj       = (const int*)d_in[1];
    const int*   mask      = (const int*)d_in[2];
    const int*   item      = (const int*)d_in[3];
    const int*   first_adj = (const int*)d_in[4];
    const int*   adj_all   = (const int*)d_in[5];
    const float* emb       = (const float*)d_in[6];
    const float* a_local   = (const float*)d_in[7];
    const float* gw1       = (const float*)d_in[8];
    const float* gw2       = (const float*)d_in[9];
    const float* gw3       = (const float*)d_in[10];
    const float* gbias     = (const float*)d_in[11];
    float* out = (float*)d_out;

    float* o0a_dev = nullptr;
    float* o0b_dev = nullptr;
    cudaGetSymbolAddress((void**)&o0a_dev, g_o0a);
    cudaGetSymbolAddress((void**)&o0b_dev, g_o0b);
    float* ev0_dev = nullptr;
    float* ev1_dev = nullptr;
    cudaGetSymbolAddress((void**)&ev0_dev, g_ev0);
    cudaGetSymbolAddress((void**)&ev1_dev, g_ev1);
    float* ev2_dev = nullptr;
    cudaGetSymbolAddress((void**)&ev2_dev, g_ev2);

    sess_kernel<<<BB, DIMN>>>(item, mask, emb);

    int rows = BB * (N0 + N1 + N2);
    gather_kernel<<<(rows * 32 + 255) / 256, 256>>>(inputs, first_adj, adj_all, emb);

    local_kernel<<<BB, 256>>>(adj, a_local, out);

    const float* w1h0 = gw1;   const float* w1h1 = gw1 + DIMN * DIMN;
    const float* w2h0 = gw2;   const float* w2h1 = gw2 + DIMN;
    const float* w3h0 = gw3;   const float* w3h1 = gw3 + 2 * DIMN * DIMN;
    const float* bh0  = gbias; const float* bh1  = gbias + DIMN;

    // ---- hop 0, stage a: self=ev0, neigh=ev1 (K=12) ----
    {
        int total = BB * N0 * 12;                       // 76800 score rows
        score_gemm<<<(total + 127) / 128, 256>>>(ev1_dev, w1h0, w2h0, N0 * 12, total);
        int nodes = BB * N0;
        softagg_kernel<12><<<(nodes + 7) / 8, 256>>>(ev1_dev, nodes);
        out_gemm<0><<<(nodes + 127) / 128, 256>>>(ev0_dev, w3h0, bh0, o0a_dev, nodes);
    }
    // ---- hop 0, stage b: self=ev1, neigh=ev2 (K=2) ----
    {
        int total = BB * N1 * 2;                        // 153600 score rows
        score_gemm<<<(total + 127) / 128, 256>>>(ev2_dev, w1h0, w2h0, N1 * 2, total);
        int nodes = BB * N1;
        softagg_kernel<2><<<(nodes + 7) / 8, 256>>>(ev2_dev, nodes);
        out_gemm<0><<<(nodes + 127) / 128, 256>>>(ev1_dev, w3h0, bh0, o0b_dev, nodes);
    }
    // ---- hop 1: self=o0a, neigh=o0b (K=12), accumulate into d_out ----
    {
        int total = BB * N0 * 12;
        score_gemm<<<(total + 127) / 128, 256>>>(o0b_dev, w1h1, w2h1, N0 * 12, total);
        int nodes = BB * N0;
        softagg_kernel<12><<<(nodes + 7) / 8, 256>>>(o0b_dev, nodes);
        out_gemm<1><<<(nodes + 127) / 128, 256>>>(o0a_dev, w3h1, bh1, out, nodes);
    }
}

// round 12
// speedup vs baseline: 1.0026x; 1.0026x over previous
#include <cuda_runtime.h>
#include <cstdint>
#include <cstddef>

#define BB   128
#define SS   50
#define DIMN 128
#define N0   50
#define N1   600
#define N2   1200

// ---------------- scratch (static device globals; no allocation) ----------------
__device__ float g_sess[BB * DIMN];
__device__ float g_ev0[BB * N0 * DIMN];
__device__ float g_ev1[BB * N1 * DIMN];
__device__ float g_ev2[(size_t)BB * N2 * DIMN];
__device__ float g_agg[BB * N1 * DIMN];
__device__ float g_o0a[BB * N0 * DIMN];
__device__ float g_o0b[BB * N1 * DIMN];
__device__ float g_score[BB * N1 * 2];     // max 153600 scores

__device__ __forceinline__ float leaky(float x) { return x >= 0.f ? x : 0.2f * x; }

__device__ __forceinline__ uint32_t f2tf(float x) {
    uint32_t o;
    asm("cvt.rna.tf32.f32 %0, %1;" : "=r"(o) : "f"(x));
    return o;
}

__device__ __forceinline__ void mma_tf32(float c[4], uint32_t a0, uint32_t a1, uint32_t a2,
                                         uint32_t a3, uint32_t b0, uint32_t b1) {
    asm volatile(
        "mma.sync.aligned.m16n8k8.row.col.f32.tf32.tf32.f32 "
        "{%0,%1,%2,%3}, {%4,%5,%6,%7}, {%8,%9}, {%0,%1,%2,%3};\n"
        : "+f"(c[0]), "+f"(c[1]), "+f"(c[2]), "+f"(c[3])
        : "r"(a0), "r"(a1), "r"(a2), "r"(a3), "r"(b0), "r"(b1));
}

#define AST 36    // A smem stride (floats), 4 mod 32 -> conflict-free frag loads
#define BST 136   // B smem stride (floats), 8 mod 32 -> conflict-free frag loads

// ---------------- session mean embedding ----------------
__global__ void sess_kernel(const int* __restrict__ item, const int* __restrict__ mask,
                            const float* __restrict__ emb) {
    int b = blockIdx.x, d = threadIdx.x;
    float acc = 0.f, ms = 0.f;
    for (int s = 0; s < SS; s++) {
        float m = (float)mask[b * SS + s];
        ms += m;
        int node = item[b * SS + s];
        acc += m * emb[(size_t)node * DIMN + d];
    }
    g_sess[b * DIMN + d] = acc / ms;
}

// ---------------- gather ev0/ev1/ev2 (warp per row, float4) ----------------
__global__ void gather_kernel(const int* __restrict__ inputs, const int* __restrict__ first_adj,
                              const int* __restrict__ adj_all, const float* __restrict__ emb) {
    int warp = (blockIdx.x * blockDim.x + threadIdx.x) >> 5;
    int lane = threadIdx.x & 31;
    const int R0 = BB * N0, R1 = BB * N1, R2 = BB * N2;
    if (warp >= R0 + R1 + R2) return;
    int node;
    float* dst;
    if (warp < R0) {
        node = inputs[warp];
        dst = g_ev0 + (size_t)warp * DIMN;
    } else if (warp < R0 + R1) {
        int r1 = warp - R0;
        node = first_adj[r1];
        dst = g_ev1 + (size_t)r1 * DIMN;
    } else {
        int r2 = warp - R0 - R1;
        int b = r2 / N2, j = r2 % N2;
        int n = j >> 1, jj = j & 1;
        int p = first_adj[b * N1 + n];
        node = adj_all[p * 2 + jj];
        dst = g_ev2 + (size_t)r2 * DIMN;
    }
    const float4* src = (const float4*)(emb + (size_t)node * DIMN);
    ((float4*)dst)[lane] = src[lane];
}

// ---------------- local GAT (one block per batch element) ----------------
__global__ __launch_bounds__(256) void local_kernel(const int* __restrict__ adj,
                                                    const float* __restrict__ a_local,
                                                    float* __restrict__ out) {
    __shared__ __align__(16) float hs[SS * DIMN];
    __shared__ __align__(16) float als[4 * DIMN];
    __shared__ float att[SS][SS];
    int b = blockIdx.x, t = threadIdx.x;
    for (int i = t; i < SS * DIMN; i += 256) hs[i] = g_ev0[(size_t)b * SS * DIMN + i];
    for (int i = t; i < 4 * DIMN; i += 256) als[i] = a_local[i];
    __syncthreads();
    for (int p = t; p < SS * SS; p += 256) {
        int i = p / SS, j = p % SS;
        int a = adj[(size_t)b * SS * SS + p];
        float v;
        if (a == 0) {
            v = -9e15f;
        } else {
            int k = a - 1;
            const float4* hi = (const float4*)(hs + i * DIMN);
            const float4* hj = (const float4*)(hs + j * DIMN);
            const float4* ak = (const float4*)(als + k * DIMN);
            float acc = 0.f;
#pragma unroll
            for (int q = 0; q < 32; q++) {
                float4 x = hi[q], y = hj[q], z = ak[q];
                acc += x.x * y.x * z.x + x.y * y.y * z.y + x.z * y.z * z.z + x.w * y.w * z.w;
            }
            v = leaky(acc);
        }
        att[i][j] = v;
    }
    __syncthreads();
    int w = t >> 5, lane = t & 31;
    for (int i = w; i < SS; i += 8) {
        float v0 = att[i][lane];
        float v1 = (lane + 32 < SS) ? att[i][lane + 32] : -3.4e38f;
        float m = fmaxf(v0, v1);
        for (int off = 16; off; off >>= 1) m = fmaxf(m, __shfl_xor_sync(0xffffffffu, m, off));
        float e0 = expf(v0 - m);
        float e1 = (lane + 32 < SS) ? expf(v1 - m) : 0.f;
        float s = e0 + e1;
        for (int off = 16; off; off >>= 1) s += __shfl_xor_sync(0xffffffffu, s, off);
        att[i][lane] = e0 / s;
        if (lane + 32 < SS) att[i][lane + 32] = e1 / s;
    }
    __syncthreads();
    for (int idx = t; idx < SS * DIMN; idx += 256) {
        int i = idx >> 7, d = idx & 127;
        float acc = 0.f;
        for (int j = 0; j < SS; j++) acc += att[i][j] * hs[j * DIMN + d];
        out[(size_t)b * SS * DIMN + idx] = acc;
    }
}

// ---------------- attention-score GEMM (tf32 tensor cores) ----------------
// S[row] = sum_e leaky( sum_d (sess[b,d]*neigh[row,d]) * W1[d,e] ) * w2[e]
// Tile: 128 rows x N=128, K=128 in 4 chunks of 32. 8 warps, warp = 16 rows.
__global__ __launch_bounds__(256, 2) void score_gemm(const float* __restrict__ neigh,
                                                     const float* __restrict__ w1,
                                                     const float* __restrict__ w2,
                                                     int rowsPerB, int total) {
    __shared__ __align__(16) float As[128 * AST];
    __shared__ __align__(16) float Bs[32 * BST];
    __shared__ float w2s[DIMN];
    int t = threadIdx.x;
    int warp = t >> 5, lane = t & 31, gr = lane >> 2, ctg = lane & 3;
    if (t < DIMN) w2s[t] = w2[t];
    int rowBase0 = blockIdx.x * 128;

    float c[16][4];
#pragma unroll
    for (int nt = 0; nt < 16; nt++)
#pragma unroll
        for (int q = 0; q < 4; q++) c[nt][q] = 0.f;

    for (int kc = 0; kc < 4; kc++) {
        // load A chunk (128 x 32): X = sess (.) neigh, converted to tf32
#pragma unroll
        for (int i = 0; i < 4; i++) {
            int id = t + i * 256;
            int r = id >> 3, c4 = (id & 7) * 4;
            int rr = rowBase0 + r;
            float4 v = make_float4(0.f, 0.f, 0.f, 0.f);
            if (rr < total) {
                int b = rr / rowsPerB;
                float4 nv = *(const float4*)(neigh + (size_t)rr * DIMN + kc * 32 + c4);
                float4 sv = *(const float4*)(g_sess + b * DIMN + kc * 32 + c4);
                v.x = nv.x * sv.x; v.y = nv.y * sv.y; v.z = nv.z * sv.z; v.w = nv.w * sv.w;
            }
            uint4 o;
            o.x = f2tf(v.x); o.y = f2tf(v.y); o.z = f2tf(v.z); o.w = f2tf(v.w);
            *(uint4*)(&As[r * AST + c4]) = o;
        }
        // load B chunk (32 x 128) from W1
#pragma unroll
        for (int i = 0; i < 4; i++) {
            int id = t + i * 256;
            int k = id >> 5, c4 = (id & 31) * 4;
            float4 wv = *(const float4*)(w1 + (size_t)(kc * 32 + k) * DIMN + c4);
            uint4 o;
            o.x = f2tf(wv.x); o.y = f2tf(wv.y); o.z = f2tf(wv.z); o.w = f2tf(wv.w);
            *(uint4*)(&Bs[k * BST + c4]) = o;
        }
        __syncthreads();
        int rb = warp * 16;
#pragma unroll
        for (int ks = 0; ks < 4; ks++) {
            int k0 = ks * 8;
            uint32_t a0 = __float_as_uint(As[(rb + gr) * AST + k0 + ctg]);
            uint32_t a1 = __float_as_uint(As[(rb + gr + 8) * AST + k0 + ctg]);
            uint32_t a2 = __float_as_uint(As[(rb + gr) * AST + k0 + ctg + 4]);
            uint32_t a3 = __float_as_uint(As[(rb + gr + 8) * AST + k0 + ctg + 4]);
#pragma unroll
            for (int nt = 0; nt < 16; nt++) {
                int n0 = nt * 8;
                uint32_t b0 = __float_as_uint(Bs[(k0 + ctg) * BST + n0 + gr]);
                uint32_t b1 = __float_as_uint(Bs[(k0 + ctg + 4) * BST + n0 + gr]);
                mma_tf32(c[nt], a0, a1, a2, a3, b0, b1);
            }
        }
        __syncthreads();
    }
    // epilogue: leaky, *w2, row-reduce
    float p0 = 0.f, p1 = 0.f;
#pragma unroll
    for (int nt = 0; nt < 16; nt++) {
        int col0 = nt * 8 + 2 * ctg;
        float w20 = w2s[col0], w21 = w2s[col0 + 1];
        p0 += leaky(c[nt][0]) * w20 + leaky(c[nt][1]) * w21;
        p1 += leaky(c[nt][2]) * w20 + leaky(c[nt][3]) * w21;
    }
    p0 += __shfl_xor_sync(0xffffffffu, p0, 1);
    p0 += __shfl_xor_sync(0xffffffffu, p0, 2);
    p1 += __shfl_xor_sync(0xffffffffu, p1, 1);
    p1 += __shfl_xor_sync(0xffffffffu, p1, 2);
    if (ctg == 0) {
        int r0 = rowBase0 + warp * 16 + gr;
        if (r0 < total) g_score[r0] = p0;
        if (r0 + 8 < total) g_score[r0 + 8] = p1;
    }
}

// ---------------- softmax over K + weighted aggregation (warp per node) ----------------
template <int K>
__global__ void softagg_kernel(const float* __restrict__ neigh, int nodes) {
    int warp = (blockIdx.x * blockDim.x + threadIdx.x) >> 5;
    int lane = threadIdx.x & 31;
    if (warp >= nodes) return;
    float s = (lane < K) ? g_score[warp * K + lane] : -3.4e38f;
    float m = s;
    for (int off = 16; off; off >>= 1) m = fmaxf(m, __shfl_xor_sync(0xffffffffu, m, off));
    float e = (lane < K) ? expf(s - m) : 0.f;
    float sum = e;
    for (int off = 16; off; off >>= 1) sum += __shfl_xor_sync(0xffffffffu, sum, off);
    float a = e / sum;
    float4 acc = make_float4(0.f, 0.f, 0.f, 0.f);
#pragma unroll
    for (int k = 0; k < K; k++) {
        float ak = __shfl_sync(0xffffffffu, a, k);
        float4 v = *(const float4*)(neigh + ((size_t)warp * K + k) * DIMN + lane * 4);
        acc.x += ak * v.x; acc.y += ak * v.y; acc.z += ak * v.z; acc.w += ak * v.w;
    }
    *(float4*)(g_agg + (size_t)warp * DIMN + lane * 4) = acc;
}

// ---------------- output transform GEMM: relu(concat(self,agg) @ W3 + bias) ----------------
// Tile: 128 rows x N=128, K=256 in 8 chunks of 32. ACC: 0 write, 1 accumulate into out.
template <int ACC>
__global__ __launch_bounds__(256, 2) void out_gemm(const float* __restrict__ self_,
                                                   const float* __restrict__ w3,
                                                   const float* __restrict__ bias,
                                                   float* __restrict__ out, int rows) {
    __shared__ __align__(16) float As[128 * AST];
    __shared__ __align__(16) float Bs[32 * BST];
    __shared__ float bs[DIMN];
    int t = threadIdx.x;
    int warp = t >> 5, lane = t & 31, gr = lane >> 2, ctg = lane & 3;
    if (t < DIMN) bs[t] = bias[t];
    int rowBase0 = blockIdx.x * 128;

    float c[16][4];
#pragma unroll
    for (int nt = 0; nt < 16; nt++)
#pragma unroll
        for (int q = 0; q < 4; q++) c[nt][q] = 0.f;

    for (int kc = 0; kc < 8; kc++) {
        const float* src = (kc < 4) ? self_ : g_agg;
        int dbase = (kc < 4) ? kc * 32 : (kc - 4) * 32;
#pragma unroll
        for (int i = 0; i < 4; i++) {
            int id = t + i * 256;
            int r = id >> 3, c4 = (id & 7) * 4;
            int rr = rowBase0 + r;
            float4 v = make_float4(0.f, 0.f, 0.f, 0.f);
            if (rr < rows) v = *(const float4*)(src + (size_t)rr * DIMN + dbase + c4);
            uint4 o;
            o.x = f2tf(v.x); o.y = f2tf(v.y); o.z = f2tf(v.z); o.w = f2tf(v.w);
            *(uint4*)(&As[r * AST + c4]) = o;
        }
#pragma unroll
        for (int i = 0; i < 4; i++) {
            int id = t + i * 256;
            int k = id >> 5, c4 = (id & 31) * 4;
            float4 wv = *(const float4*)(w3 + (size_t)(kc * 32 + k) * DIMN + c4);
            uint4 o;
            o.x = f2tf(wv.x); o.y = f2tf(wv.y); o.z = f2tf(wv.z); o.w = f2tf(wv.w);
            *(uint4*)(&Bs[k * BST + c4]) = o;
        }
        __syncthreads();
        int rb = warp * 16;
#pragma unroll
        for (int ks = 0; ks < 4; ks++) {
            int k0 = ks * 8;
            uint32_t a0 = __float_as_uint(As[(rb + gr) * AST + k0 + ctg]);
            uint32_t a1 = __float_as_uint(As[(rb + gr + 8) * AST + k0 + ctg]);
            uint32_t a2 = __float_as_uint(As[(rb + gr) * AST + k0 + ctg + 4]);
            uint32_t a3 = __float_as_uint(As[(rb + gr + 8) * AST + k0 + ctg + 4]);
#pragma unroll
            for (int nt = 0; nt < 16; nt++) {
                int n0 = nt * 8;
                uint32_t b0 = __float_as_uint(Bs[(k0 + ctg) * BST + n0 + gr]);
                uint32_t b1 = __float_as_uint(Bs[(k0 + ctg + 4) * BST + n0 + gr]);
                mma_tf32(c[nt], a0, a1, a2, a3, b0, b1);
            }
        }
        __syncthreads();
    }
    // epilogue: + bias, relu, store / accumulate
    int r0 = rowBase0 + warp * 16 + gr;
    int r1 = r0 + 8;
#pragma unroll
    for (int nt = 0; nt < 16; nt++) {
        int col0 = nt * 8 + 2 * ctg;
        float z00 = fmaxf(c[nt][0] + bs[col0], 0.f);
        float z01 = fmaxf(c[nt][1] + bs[col0 + 1], 0.f);
        float z10 = fmaxf(c[nt][2] + bs[col0], 0.f);
        float z11 = fmaxf(c[nt][3] + bs[col0 + 1], 0.f);
        if (r0 < rows) {
            if (ACC) {
                out[(size_t)r0 * DIMN + col0] += z00;
                out[(size_t)r0 * DIMN + col0 + 1] += z01;
            } else {
                out[(size_t)r0 * DIMN + col0] = z00;
                out[(size_t)r0 * DIMN + col0 + 1] = z01;
            }
        }
        if (r1 < rows) {
            if (ACC) {
                out[(size_t)r1 * DIMN + col0] += z10;
                out[(size_t)r1 * DIMN + col0 + 1] += z11;
            } else {
                out[(size_t)r1 * DIMN + col0] = z10;
                out[(size_t)r1 * DIMN + col0 + 1] = z11;
            }
        }
    }
}

// ---------------- launch ----------------
extern "C" void kernel_launch(void* const* d_in, const int* in_sizes, int n_in,
                              void* d_out, int out_size) {
    const int*   inputs    = (const int*)d_in[0];
    const int*   adj       = (const int*)d_in[1];
    const int*   mask      = (const int*)d_in[2];
    const int*   item      = (const int*)d_in[3];
    const int*   first_adj = (const int*)d_in[4];
    const int*   adj_all   = (const int*)d_in[5];
    const float* emb       = (const float*)d_in[6];
    const float* a_local   = (const float*)d_in[7];
    const float* gw1       = (const float*)d_in[8];
    const float* gw2       = (const float*)d_in[9];
    const float* gw3       = (const float*)d_in[10];
    const float* gbias     = (const float*)d_in[11];
    float* out = (float*)d_out;

    float* o0a_dev = nullptr;
    float* o0b_dev = nullptr;
    cudaGetSymbolAddress((void**)&o0a_dev, g_o0a);
    cudaGetSymbolAddress((void**)&o0b_dev, g_o0b);
    float* ev0_dev = nullptr;
    float* ev1_dev = nullptr;
    cudaGetSymbolAddress((void**)&ev0_dev, g_ev0);
    cudaGetSymbolAddress((void**)&ev1_dev, g_ev1);
    float* ev2_dev = nullptr;
    cudaGetSymbolAddress((void**)&ev2_dev, g_ev2);

    sess_kernel<<<BB, DIMN>>>(item, mask, emb);

    int rows = BB * (N0 + N1 + N2);
    gather_kernel<<<(rows * 32 + 255) / 256, 256>>>(inputs, first_adj, adj_all, emb);

    local_kernel<<<BB, 256>>>(adj, a_local, out);

    const float* w1h0 = gw1;   const float* w1h1 = gw1 + DIMN * DIMN;
    const float* w2h0 = gw2;   const float* w2h1 = gw2 + DIMN;
    const float* w3h0 = gw3;   const float* w3h1 = gw3 + 2 * DIMN * DIMN;
    const float* bh0  = gbias; const float* bh1  = gbias + DIMN;

    // ---- hop 0, stage a: self=ev0, neigh=ev1 (K=12) ----
    {
        int total = BB * N0 * 12;                       // 76800 score rows
        score_gemm<<<(total + 127) / 128, 256>>>(ev1_dev, w1h0, w2h0, N0 * 12, total);
        int nodes = BB * N0;
        softagg_kernel<12><<<(nodes + 7) / 8, 256>>>(ev1_dev, nodes);
        out_gemm<0><<<(nodes + 127) / 128, 256>>>(ev0_dev, w3h0, bh0, o0a_dev, nodes);
    }
    // ---- hop 0, stage b: self=ev1, neigh=ev2 (K=2) ----
    {
        int total = BB * N1 * 2;                        // 153600 score rows
        score_gemm<<<(total + 127) / 128, 256>>>(ev2_dev, w1h0, w2h0, N1 * 2, total);
        int nodes = BB * N1;
        softagg_kernel<2><<<(nodes + 7) / 8, 256>>>(ev2_dev, nodes);
        out_gemm<0><<<(nodes + 127) / 128, 256>>>(ev1_dev, w3h0, bh0, o0b_dev, nodes);
    }
    // ---- hop 1: self=o0a, neigh=o0b (K=12), accumulate into d_out ----
    {
        int total = BB * N0 * 12;
        score_gemm<<<(total + 127) / 128, 256>>>(o0b_dev, w1h1, w2h1, N0 * 12, total);
        int nodes = BB * N0;
        softagg_kernel<12><<<(nodes + 7) / 8, 256>>>(o0b_dev, nodes);
        out_gemm<1><<<(nodes + 127) / 128, 256>>>(o0a_dev, w3h1, bh1, out, nodes);
    }
}